// round 17
// baseline (speedup 1.0000x reference)
#include <cuda_runtime.h>
#include <cuda_fp16.h>
#include <cstdint>

#define NNODES 2048
#define JDIM   768      // F_IN * T = 32*24
#define KCHEB  3
#define BATCH  16
#define FOUT   64
#define TDIM   24
#define KF     96       // KCHEB * F_IN

// 151 MB fp16 scratch: half2{rhs[b][m][kf][t], rhs[..][t+1]} at [b*2048+m][kf][t/2]
__device__ uint32_t g_rhsh[(size_t)BATCH * NNODES * KF * (TDIM / 2)];
// 50 MB pre-packed x: half2{x[b][2np][j], x[b][2np+1][j]} at [b][np][j]
__device__ uint32_t g_xh[(size_t)BATCH * (NNODES / 2) * JDIM];
// 12 KB Theta as half2 pairs over kf: g_thh[kp][o] = h2(Theta[2kp][o], Theta[2kp+1][o])
__device__ uint32_t g_thh[(KF / 2) * FOUT];

__device__ __forceinline__ uint32_t pack_h2(float lo, float hi) {
    __half2 h = __floats2half2_rn(lo, hi);
    return *reinterpret_cast<uint32_t*>(&h);
}
__device__ __forceinline__ uint32_t smem_u32(const void* p) {
    uint32_t a;
    asm("{ .reg .u64 t; cvta.to.shared.u64 t, %1; cvt.u32.u64 %0, t; }" : "=r"(a) : "l"(p));
    return a;
}
__device__ __forceinline__ void cp16(uint32_t dst, const void* src) {
    asm volatile("cp.async.ca.shared.global [%0], [%1], 16;" :: "r"(dst), "l"(src) : "memory");
}
__device__ __forceinline__ void mma_fp16(float d[4], const uint32_t a[4], const uint32_t b[2]) {
    asm("mma.sync.aligned.m16n8k16.row.col.f32.f16.f16.f32 "
        "{%0,%1,%2,%3}, {%4,%5,%6,%7}, {%8,%9}, {%0,%1,%2,%3};"
        : "+f"(d[0]), "+f"(d[1]), "+f"(d[2]), "+f"(d[3])
        : "r"(a[0]), "r"(a[1]), "r"(a[2]), "r"(a[3]),
          "r"(b[0]), "r"(b[1]));
}

// ---------------------------------------------------------------------------
// Prepack x: g_xh[b][np][j] = half2(x[b][2np][j], x[b][2np+1][j])
// ---------------------------------------------------------------------------
__global__ void __launch_bounds__(256)
prepack_kernel(const float* __restrict__ x)
{
    const int idx = blockIdx.x * 256 + threadIdx.x;
    const int b  = idx / (1024 * 192);
    const int r  = idx % (1024 * 192);
    const int np = r / 192;
    const int j4 = (r % 192) << 2;
    const size_t s0 = (size_t)(b * NNODES + (np << 1)) * JDIM + j4;
    const float4 a0 = *(const float4*)(x + s0);
    const float4 a1 = *(const float4*)(x + s0 + JDIM);
    uint4 o;
    o.x = pack_h2(a0.x, a1.x);  o.y = pack_h2(a0.y, a1.y);
    o.z = pack_h2(a0.z, a1.z);  o.w = pack_h2(a0.w, a1.w);
    *(uint4*)(g_xh + (size_t)(b * 1024 + np) * JDIM + j4) = o;
}

// Prepack Theta: pairs over adjacent kf rows
__global__ void __launch_bounds__(256)
theta_prepack_kernel(const float* __restrict__ Theta)
{
    const int i  = blockIdx.x * 256 + threadIdx.x;   // 0..3071
    const int kp = i >> 6, o = i & 63;
    g_thh[i] = pack_h2(Theta[(kp << 1) * FOUT + o],
                       Theta[((kp << 1) + 1) * FOUT + o]);
}

// ---------------------------------------------------------------------------
// Stage 1 (frozen — at the legacy fp16 mma issue floor, ~1215 us)
// ---------------------------------------------------------------------------
__global__ void __launch_bounds__(256)
stage1_kernel(const float* __restrict__ att,
              const float* __restrict__ cheb)
{
    const int k  = blockIdx.z % KCHEB;
    const int b  = blockIdx.z / KCHEB;
    const int m0 = blockIdx.y << 7;
    const int j0 = blockIdx.x << 8;

    const float* __restrict__ Ac = cheb + (size_t)k * NNODES * NNODES;
    const float* __restrict__ Aa = att  + (size_t)b * NNODES * NNODES;

    __shared__ __align__(16) uint32_t As[2][16][136];
    __shared__ __align__(16) uint32_t Bs[2][16][264];

    const int tid  = threadIdx.x;
    const int lane = tid & 31;
    const int warp = tid >> 5;
    const int wm = (warp >> 2) << 6;
    const int wj = (warp & 3) << 6;
    const int g  = lane >> 2;
    const int ti = lane & 3;

    float acc[4][8][4];
#pragma unroll
    for (int i = 0; i < 4; ++i)
#pragma unroll
        for (int j = 0; j < 8; ++j)
#pragma unroll
            for (int c = 0; c < 4; ++c) acc[i][j][c] = 0.0f;

    float4 rc0[2], rc1[2], ra0[2], ra1[2];

    auto loadA = [&](int c) {
        const int n0 = c << 5;
#pragma unroll
        for (int i = 0; i < 2; ++i) {
            const int u  = tid + (i << 8);
            const int np = u >> 5;
            const int q  = u & 31;
            const size_t ro = (size_t)(n0 + (np << 1)) * NNODES + m0;
            rc0[i] = *((const float4*)(Ac + ro) + q);
            rc1[i] = *((const float4*)(Ac + ro + NNODES) + q);
            ra0[i] = *((const float4*)(Aa + ro) + q);
            ra1[i] = *((const float4*)(Aa + ro + NNODES) + q);
        }
    };
    auto storeA = [&](int nb) {
#pragma unroll
        for (int i = 0; i < 2; ++i) {
            const int u  = tid + (i << 8);
            const int np = u >> 5;
            const int q  = u & 31;
            uint4 ua;
            ua.x = pack_h2(rc0[i].x * ra0[i].x, rc1[i].x * ra1[i].x);
            ua.y = pack_h2(rc0[i].y * ra0[i].y, rc1[i].y * ra1[i].y);
            ua.z = pack_h2(rc0[i].z * ra0[i].z, rc1[i].z * ra1[i].z);
            ua.w = pack_h2(rc0[i].w * ra0[i].w, rc1[i].w * ra1[i].w);
            *(uint4*)&As[nb][np][q << 2] = ua;
        }
    };
    auto loadB = [&](int c, int nb) {
        const uint32_t base = smem_u32(&Bs[nb][0][0]);
        const uint32_t* src = g_xh + (size_t)(b * 1024 + (c << 4)) * JDIM + j0;
#pragma unroll
        for (int i = 0; i < 4; ++i) {
            const int l  = tid + (i << 8);
            const int np = l >> 6;
            const int o4 = (l & 63) << 2;
            cp16(base + (uint32_t)(np * 264 + o4) * 4, src + np * JDIM + o4);
        }
        asm volatile("cp.async.commit_group;" ::: "memory");
    };

    auto compute = [&](int buf) {
#pragma unroll
        for (int s = 0; s < 2; ++s) {
            const int r0 = (s << 3) + ti;
            const int r1 = r0 + 4;
            uint32_t af[4][4], bf[8][2];
#pragma unroll
            for (int i = 0; i < 4; ++i) {
                const int mi = wm + (i << 4);
                af[i][0] = As[buf][r0][mi + g];
                af[i][1] = As[buf][r0][mi + g + 8];
                af[i][2] = As[buf][r1][mi + g];
                af[i][3] = As[buf][r1][mi + g + 8];
            }
#pragma unroll
            for (int j = 0; j < 8; ++j) {
                const int nj = wj + (j << 3);
                bf[j][0] = Bs[buf][r0][nj + g];
                bf[j][1] = Bs[buf][r1][nj + g];
            }
#pragma unroll
            for (int i = 0; i < 4; ++i)
#pragma unroll
                for (int j = 0; j < 8; ++j)
                    mma_fp16(acc[i][j], af[i], bf[j]);
        }
    };

    loadA(0);
    loadB(0, 0);
    storeA(0);
    asm volatile("cp.async.wait_group 0;" ::: "memory");
    __syncthreads();

    for (int c = 0; c < 64; ++c) {
        const int buf = c & 1, nb = buf ^ 1;
        if (c < 63) {
            loadB(c + 1, nb);
            loadA(c + 1);
        }
        compute(buf);
        if (c < 63) {
            storeA(nb);
            asm volatile("cp.async.wait_group 0;" ::: "memory");
        }
        __syncthreads();
    }

    // Epilogue: pairs (jj, jj+1) = (t, t+1), t even; write half2 to g_rhsh
    const int jb = j0 + wj + (ti << 1);
#pragma unroll
    for (int i = 0; i < 4; ++i) {
#pragma unroll
        for (int h = 0; h < 2; ++h) {
            const int row = m0 + wm + (i << 4) + g + (h << 3);
            uint32_t* obase = g_rhsh
                            + ((size_t)(b * NNODES) + row) * (KF * 12)
                            + k * 32 * 12;
#pragma unroll
            for (int j = 0; j < 8; ++j) {
                const int jj = jb + (j << 3);
                const int f  = jj / 24;
                const int t  = jj - f * 24;
                obase[f * 12 + (t >> 1)] =
                    pack_h2(acc[i][j][h << 1], acc[i][j][(h << 1) + 1]);
            }
        }
    }
}

// ---------------------------------------------------------------------------
// Stage 2 v8 (fp16 tensor, zero smem, software-pipelined B):
//   out(64o x 24t) = Theta^T(64 x 96kf) * rhs(96kf x 24t) per row.
// fp16 m16n8k16: o = 4 m-tiles, t = 3 n-tiles, kf = 6 k-steps of 16.
// 128 threads = 4 warps, one row per warp, 4 rows/CTA, grid 8192.
// The 12 raw rhs words of k-step ks+1 are prefetched into registers before
// the mma block of step ks (doubles per-warp outstanding-load window).
// A frags load-at-use from the L1-resident 12KB g_thh table.
// ---------------------------------------------------------------------------
__global__ void __launch_bounds__(128)
stage2_kernel(float* __restrict__ out)
{
    const int tid  = threadIdx.x;
    const int w    = tid >> 5;
    const int lane = tid & 31;
    const int g    = lane >> 2;
    const int ti   = lane & 3;

    const size_t row = (size_t)blockIdx.x * 4 + w;
    const uint32_t* __restrict__ Rb = g_rhsh + row * (KF * 12);
    const int sel = (g & 1) ? 0x7632 : 0x5410;
    const int tpb = g >> 1;

    float acc[4][3][4];
#pragma unroll
    for (int mi = 0; mi < 4; ++mi)
#pragma unroll
        for (int nt = 0; nt < 3; ++nt)
#pragma unroll
            for (int c = 0; c < 4; ++c) acc[mi][nt][c] = 0.0f;

    auto loadB = [&](int ks, uint32_t br[3][4]) {
        const int kp0 = (ks << 3) + ti;
        const int kp1 = kp0 + 4;
#pragma unroll
        for (int nt = 0; nt < 3; ++nt) {
            const int tp = (nt << 2) + tpb;
            br[nt][0] = Rb[(kp0 << 1) * 12 + tp];
            br[nt][1] = Rb[((kp0 << 1) + 1) * 12 + tp];
            br[nt][2] = Rb[(kp1 << 1) * 12 + tp];
            br[nt][3] = Rb[((kp1 << 1) + 1) * 12 + tp];
        }
    };

    uint32_t bcur[3][4];
    loadB(0, bcur);

#pragma unroll
    for (int ks = 0; ks < 6; ++ks) {
        uint32_t bnext[3][4];
        if (ks < 5) loadB(ks + 1, bnext);   // in flight during this step's mma

        const int kp0 = (ks << 3) + ti;
        const int kp1 = kp0 + 4;
        uint32_t af[4][4], bf[3][2];
#pragma unroll
        for (int mi = 0; mi < 4; ++mi) {
            const int o = (mi << 4) + g;
            af[mi][0] = g_thh[(kp0 << 6) + o];
            af[mi][1] = g_thh[(kp0 << 6) + o + 8];
            af[mi][2] = g_thh[(kp1 << 6) + o];
            af[mi][3] = g_thh[(kp1 << 6) + o + 8];
        }
#pragma unroll
        for (int nt = 0; nt < 3; ++nt) {
            bf[nt][0] = __byte_perm(bcur[nt][0], bcur[nt][1], sel);
            bf[nt][1] = __byte_perm(bcur[nt][2], bcur[nt][3], sel);
        }
#pragma unroll
        for (int mi = 0; mi < 4; ++mi)
#pragma unroll
            for (int nt = 0; nt < 3; ++nt)
                mma_fp16(acc[mi][nt], af[mi], bf[nt]);

        if (ks < 5) {
#pragma unroll
            for (int nt = 0; nt < 3; ++nt)
#pragma unroll
                for (int q = 0; q < 4; ++q) bcur[nt][q] = bnext[nt][q];
        }
    }

    // epilogue: c0:(g,2ti) c1:(g,2ti+1) c2:(g+8,2ti) c3:(g+8,2ti+1)
    float* ob = out + row * (FOUT * TDIM);
#pragma unroll
    for (int mi = 0; mi < 4; ++mi) {
        const int o = (mi << 4) + g;
#pragma unroll
        for (int nt = 0; nt < 3; ++nt) {
            const int t = (nt << 3) + (ti << 1);
            float2 v0 = make_float2(fmaxf(acc[mi][nt][0], 0.0f),
                                    fmaxf(acc[mi][nt][1], 0.0f));
            float2 v1 = make_float2(fmaxf(acc[mi][nt][2], 0.0f),
                                    fmaxf(acc[mi][nt][3], 0.0f));
            *(float2*)(ob + o * TDIM + t) = v0;
            *(float2*)(ob + (o + 8) * TDIM + t) = v1;
        }
    }
}

// ---------------------------------------------------------------------------
extern "C" void kernel_launch(void* const* d_in, const int* in_sizes, int n_in,
                              void* d_out, int out_size)
{
    (void)in_sizes; (void)n_in; (void)out_size;
    const float* x     = (const float*)d_in[0];   // (16,2048,32,24)
    const float* att   = (const float*)d_in[1];   // (16,2048,2048)
    const float* cheb  = (const float*)d_in[2];   // (3,2048,2048)
    const float* Theta = (const float*)d_in[3];   // (3,32,64)
    float* out = (float*)d_out;                   // (16,2048,64,24)

    prepack_kernel<<<BATCH * 1024 * 192 / 256, 256>>>(x);
    theta_prepack_kernel<<<(KF / 2) * FOUT / 256, 256>>>(Theta);
    dim3 g1(JDIM / 256, NNODES / 128, KCHEB * BATCH);   // (3, 16, 48)
    stage1_kernel<<<g1, 256>>>(att, cheb);
    stage2_kernel<<<(BATCH * NNODES) / 4, 128>>>(out);
}